// round 1
// baseline (speedup 1.0000x reference)
#include <cuda_runtime.h>
#include <math.h>

#define CM    1024          // d_model
#define NH    16            // heads
#define DK    64            // head dim
#define TT    2048          // seq len
#define BB    4             // batch
#define MROWS (BB * TT)     // 8192

// ---------------- scratch (device globals; no allocation APIs allowed) ----------
__device__ float g_q[BB * NH * TT * DK];   // [b,h,t,d]  33.5 MB
__device__ float g_k[BB * NH * TT * DK];
__device__ float g_v[BB * NH * TT * DK];
__device__ float g_y[MROWS * CM];          // [b,t, h*dk] 33.5 MB

// =============================================================================
// Kernel 1: QKV projection.  C[m,n] = sum_k X[m,k] * W[n,k] + bias[n]
// (torch Linear: x @ W^T + b).  M=8192, N=3072, K=1024.
// 128x128 block, BK=8, 256 threads, 8x8 per thread, smem padded to stride 132
// (conflict-free transposed stores + aligned float4 row loads).
// Epilogue scatters into g_q / g_k / g_v with [b,h,t,d] layout.
// =============================================================================
__global__ __launch_bounds__(256, 2) void qkv_gemm(const float* __restrict__ X,
                                                   const float* __restrict__ W,
                                                   const float* __restrict__ bias) {
    __shared__ float As[8][132];
    __shared__ float Bs[8][132];
    const int K = CM;
    const int bm = blockIdx.y * 128;
    const int bn = blockIdx.x * 128;
    const int tid = threadIdx.x;
    const int tx = tid & 15, ty = tid >> 4;
    const int lrow = tid >> 1;            // 0..127
    const int lcol = (tid & 1) * 4;       // 0 or 4

    const float* Ap = X + (size_t)(bm + lrow) * K + lcol;
    const float* Bp = W + (size_t)(bn + lrow) * K + lcol;

    float acc[8][8];
#pragma unroll
    for (int i = 0; i < 8; i++)
#pragma unroll
        for (int j = 0; j < 8; j++) acc[i][j] = 0.f;

#pragma unroll 1
    for (int k0 = 0; k0 < K; k0 += 8) {
        float4 av = *(const float4*)(Ap + k0);
        float4 bv = *(const float4*)(Bp + k0);
        __syncthreads();   // previous tile's compute done before overwrite
        As[lcol + 0][lrow] = av.x; As[lcol + 1][lrow] = av.y;
        As[lcol + 2][lrow] = av.z; As[lcol + 3][lrow] = av.w;
        Bs[lcol + 0][lrow] = bv.x; Bs[lcol + 1][lrow] = bv.y;
        Bs[lcol + 2][lrow] = bv.z; Bs[lcol + 3][lrow] = bv.w;
        __syncthreads();
#pragma unroll
        for (int kk = 0; kk < 8; kk++) {
            float a[8], b[8];
            *(float4*)(a)     = *(const float4*)(&As[kk][ty * 8]);
            *(float4*)(a + 4) = *(const float4*)(&As[kk][ty * 8 + 4]);
            *(float4*)(b)     = *(const float4*)(&Bs[kk][tx * 8]);
            *(float4*)(b + 4) = *(const float4*)(&Bs[kk][tx * 8 + 4]);
#pragma unroll
            for (int i = 0; i < 8; i++)
#pragma unroll
                for (int j = 0; j < 8; j++) acc[i][j] += a[i] * b[j];
        }
    }

    // Epilogue: add bias, scatter to Q/K/V in [b,h,t,d]
    const int n0 = bn + tx * 8;
    float bvals[8];
#pragma unroll
    for (int j = 0; j < 8; j++) bvals[j] = bias[n0 + j];
    const int part = n0 >> 10;           // 0:Q 1:K 2:V   (8-col group never crosses)
    const int rem  = n0 & 1023;
    const int h    = rem >> 6;
    const int d0   = rem & 63;           // 8-col group stays inside one head
    float* dst = (part == 0) ? g_q : (part == 1) ? g_k : g_v;

#pragma unroll
    for (int i = 0; i < 8; i++) {
        const int m  = bm + ty * 8 + i;
        const int bb = m >> 11;
        const int t  = m & 2047;
        float* drow = dst + ((size_t)(bb * NH + h) * TT + t) * DK + d0;
        float4 r0, r1;
        r0.x = acc[i][0] + bvals[0]; r0.y = acc[i][1] + bvals[1];
        r0.z = acc[i][2] + bvals[2]; r0.w = acc[i][3] + bvals[3];
        r1.x = acc[i][4] + bvals[4]; r1.y = acc[i][5] + bvals[5];
        r1.z = acc[i][6] + bvals[6]; r1.w = acc[i][7] + bvals[7];
        *(float4*)(drow)     = r0;
        *(float4*)(drow + 4) = r1;
    }
}

// =============================================================================
// Kernel 2: causal flash attention, fp32, online softmax.
// Grid (T/64, B*NH). CTA: 256 threads, Br=Bc=64, dk=64.
// Qs/Ks stored transposed [d][row] stride 66 (float2 loads, low-conflict
// transposed stores); Ks buffer reused for P (row-major [r][c] stride 66).
// Causal: query block i only visits key blocks 0..i (skips 48% of work).
// =============================================================================
#define QK_STRIDE 66
#define FLASH_SMEM ((64 * QK_STRIDE * 2 + 64 * 64) * 4)   // 50176 bytes

__global__ __launch_bounds__(256, 3) void flash_kernel() {
    extern __shared__ float sm[];
    float* Qs = sm;                      // [64][66] transposed: [d][r]
    float* Ks = Qs + 64 * QK_STRIDE;     // [64][66] transposed: [d][c]; reused as Ps[r][c]
    float* Vs = Ks + 64 * QK_STRIDE;     // [64][64] natural: [c][d]

    const int bh = blockIdx.y;           // b*NH + h
    const int i0 = blockIdx.x;           // query block
    const int bb = bh >> 4;
    const int h  = bh & 15;

    const float* Qb = g_q + ((size_t)bh * TT + i0 * 64) * DK;
    const float* Kb = g_k + (size_t)bh * TT * DK;
    const float* Vb = g_v + (size_t)bh * TT * DK;

    const int tid = threadIdx.x;
    const int tx = tid & 15, ty = tid >> 4;
    const float scale = 0.125f;          // 1/sqrt(64)

    // Load Q tile transposed + pre-scaled
#pragma unroll
    for (int e = 0; e < 4; e++) {
        int lin = tid + e * 256;
        int r  = lin >> 4;
        int d4 = (lin & 15) * 4;
        float4 qv = *(const float4*)(Qb + r * DK + d4);
        Qs[(d4 + 0) * QK_STRIDE + r] = qv.x * scale;
        Qs[(d4 + 1) * QK_STRIDE + r] = qv.y * scale;
        Qs[(d4 + 2) * QK_STRIDE + r] = qv.z * scale;
        Qs[(d4 + 3) * QK_STRIDE + r] = qv.w * scale;
    }

    float m_i[4], l_i[4], o[4][4];
#pragma unroll
    for (int i = 0; i < 4; i++) {
        m_i[i] = -1e30f; l_i[i] = 0.f;
#pragma unroll
        for (int j = 0; j < 4; j++) o[i][j] = 0.f;
    }

    const int nblk = i0 + 1;
    for (int jb = 0; jb < nblk; jb++) {
        __syncthreads();   // prior iter done with Ks(Ps)/Vs; also covers Q fill at jb=0
        // Fill K (transposed) and V (natural)
#pragma unroll
        for (int e = 0; e < 4; e++) {
            int lin = tid + e * 256;
            int c  = lin >> 4;
            int d4 = (lin & 15) * 4;
            float4 kv = *(const float4*)(Kb + (size_t)(jb * 64 + c) * DK + d4);
            Ks[(d4 + 0) * QK_STRIDE + c] = kv.x;
            Ks[(d4 + 1) * QK_STRIDE + c] = kv.y;
            Ks[(d4 + 2) * QK_STRIDE + c] = kv.z;
            Ks[(d4 + 3) * QK_STRIDE + c] = kv.w;
            float4 vv = *(const float4*)(Vb + (size_t)(jb * 64 + c) * DK + d4);
            *(float4*)(&Vs[c * 64 + d4]) = vv;
        }
        __syncthreads();

        // S = (Q*scale) @ K^T   (thread owns rows 4ty..+3, cols 4tx..+3)
        float s[4][4];
#pragma unroll
        for (int i = 0; i < 4; i++)
#pragma unroll
            for (int j = 0; j < 4; j++) s[i][j] = 0.f;
#pragma unroll 16
        for (int kk = 0; kk < 64; kk++) {
            float a[4], b[4];
            float2 a0 = *(const float2*)(&Qs[kk * QK_STRIDE + 4 * ty]);
            float2 a1 = *(const float2*)(&Qs[kk * QK_STRIDE + 4 * ty + 2]);
            float2 b0 = *(const float2*)(&Ks[kk * QK_STRIDE + 4 * tx]);
            float2 b1 = *(const float2*)(&Ks[kk * QK_STRIDE + 4 * tx + 2]);
            a[0] = a0.x; a[1] = a0.y; a[2] = a1.x; a[3] = a1.y;
            b[0] = b0.x; b[1] = b0.y; b[2] = b1.x; b[3] = b1.y;
#pragma unroll
            for (int i = 0; i < 4; i++)
#pragma unroll
                for (int j = 0; j < 4; j++) s[i][j] += a[i] * b[j];
        }

        // Causal mask (diagonal block only): key col > query row
        if (jb == i0) {
#pragma unroll
            for (int i = 0; i < 4; i++)
#pragma unroll
                for (int j = 0; j < 4; j++)
                    if (4 * tx + j > 4 * ty + i) s[i][j] = -1e30f;
        }

        // Online softmax update (row stats replicated across 16 tx threads via shfl)
#pragma unroll
        for (int i = 0; i < 4; i++) {
            float rm = fmaxf(fmaxf(s[i][0], s[i][1]), fmaxf(s[i][2], s[i][3]));
            rm = fmaxf(rm, __shfl_xor_sync(0xffffffffu, rm, 1));
            rm = fmaxf(rm, __shfl_xor_sync(0xffffffffu, rm, 2));
            rm = fmaxf(rm, __shfl_xor_sync(0xffffffffu, rm, 4));
            rm = fmaxf(rm, __shfl_xor_sync(0xffffffffu, rm, 8));
            float mnew = fmaxf(m_i[i], rm);
            float p0 = __expf(s[i][0] - mnew);
            float p1 = __expf(s[i][1] - mnew);
            float p2 = __expf(s[i][2] - mnew);
            float p3 = __expf(s[i][3] - mnew);
            s[i][0] = p0; s[i][1] = p1; s[i][2] = p2; s[i][3] = p3;
            float rs = p0 + p1 + p2 + p3;
            rs += __shfl_xor_sync(0xffffffffu, rs, 1);
            rs += __shfl_xor_sync(0xffffffffu, rs, 2);
            rs += __shfl_xor_sync(0xffffffffu, rs, 4);
            rs += __shfl_xor_sync(0xffffffffu, rs, 8);
            float alpha = __expf(m_i[i] - mnew);
            l_i[i] = l_i[i] * alpha + rs;
            m_i[i] = mnew;
#pragma unroll
            for (int j = 0; j < 4; j++) o[i][j] *= alpha;
        }

        __syncthreads();   // everyone done reading Ks before overwriting with P
        // Store P row-major into the Ks buffer (contiguous float2 stores)
        float* Ps = Ks;
#pragma unroll
        for (int i = 0; i < 4; i++) {
            float2 u; u.x = s[i][0]; u.y = s[i][1];
            float2 w; w.x = s[i][2]; w.y = s[i][3];
            *(float2*)(&Ps[(4 * ty + i) * QK_STRIDE + 4 * tx])     = u;
            *(float2*)(&Ps[(4 * ty + i) * QK_STRIDE + 4 * tx + 2]) = w;
        }
        __syncthreads();

        // O += P @ V   (thread owns rows 4ty..+3, d-cols 4tx..+3)
#pragma unroll 8
        for (int c = 0; c < 64; c++) {
            float a0 = Ps[(4 * ty + 0) * QK_STRIDE + c];
            float a1 = Ps[(4 * ty + 1) * QK_STRIDE + c];
            float a2 = Ps[(4 * ty + 2) * QK_STRIDE + c];
            float a3 = Ps[(4 * ty + 3) * QK_STRIDE + c];
            float4 bv = *(const float4*)(&Vs[c * 64 + 4 * tx]);
            o[0][0] += a0 * bv.x; o[0][1] += a0 * bv.y; o[0][2] += a0 * bv.z; o[0][3] += a0 * bv.w;
            o[1][0] += a1 * bv.x; o[1][1] += a1 * bv.y; o[1][2] += a1 * bv.z; o[1][3] += a1 * bv.w;
            o[2][0] += a2 * bv.x; o[2][1] += a2 * bv.y; o[2][2] += a2 * bv.z; o[2][3] += a2 * bv.w;
            o[3][0] += a3 * bv.x; o[3][1] += a3 * bv.y; o[3][2] += a3 * bv.z; o[3][3] += a3 * bv.w;
        }
    }

    // Normalize and write to y [b, t, h*dk]
#pragma unroll
    for (int i = 0; i < 4; i++) {
        float inv = 1.0f / l_i[i];
        int t = i0 * 64 + 4 * ty + i;
        float4 r;
        r.x = o[i][0] * inv; r.y = o[i][1] * inv;
        r.z = o[i][2] * inv; r.w = o[i][3] * inv;
        *(float4*)(&g_y[((size_t)bb * TT + t) * CM + h * DK + 4 * tx]) = r;
    }
}

// =============================================================================
// Kernel 3: output projection. out[m,n] = sum_k y[m,k]*W_o[n,k] + b_o[n]
// M=8192, N=1024, K=1024. Same tiling as kernel 1.
// =============================================================================
__global__ __launch_bounds__(256, 2) void out_gemm(const float* __restrict__ W,
                                                   const float* __restrict__ bias,
                                                   float* __restrict__ out) {
    __shared__ float As[8][132];
    __shared__ float Bs[8][132];
    const int K = CM;
    const int bm = blockIdx.y * 128;
    const int bn = blockIdx.x * 128;
    const int tid = threadIdx.x;
    const int tx = tid & 15, ty = tid >> 4;
    const int lrow = tid >> 1;
    const int lcol = (tid & 1) * 4;

    const float* Ap = g_y + (size_t)(bm + lrow) * K + lcol;
    const float* Bp = W + (size_t)(bn + lrow) * K + lcol;

    float acc[8][8];
#pragma unroll
    for (int i = 0; i < 8; i++)
#pragma unroll
        for (int j = 0; j < 8; j++) acc[i][j] = 0.f;

#pragma unroll 1
    for (int k0 = 0; k0 < K; k0 += 8) {
        float4 av = *(const float4*)(Ap + k0);
        float4 bv = *(const float4*)(Bp + k0);
        __syncthreads();
        As[lcol + 0][lrow] = av.x; As[lcol + 1][lrow] = av.y;
        As[lcol + 2][lrow] = av.z; As[lcol + 3][lrow] = av.w;
        Bs[lcol + 0][lrow] = bv.x; Bs[lcol + 1][lrow] = bv.y;
        Bs[lcol + 2][lrow] = bv.z; Bs[lcol + 3][lrow] = bv.w;
        __syncthreads();
#pragma unroll
        for (int kk = 0; kk < 8; kk++) {
            float a[8], b[8];
            *(float4*)(a)     = *(const float4*)(&As[kk][ty * 8]);
            *(float4*)(a + 4) = *(const float4*)(&As[kk][ty * 8 + 4]);
            *(float4*)(b)     = *(const float4*)(&Bs[kk][tx * 8]);
            *(float4*)(b + 4) = *(const float4*)(&Bs[kk][tx * 8 + 4]);
#pragma unroll
            for (int i = 0; i < 8; i++)
#pragma unroll
                for (int j = 0; j < 8; j++) acc[i][j] += a[i] * b[j];
        }
    }

    const int n0 = bn + tx * 8;
    float bvals[8];
#pragma unroll
    for (int j = 0; j < 8; j++) bvals[j] = bias[n0 + j];
#pragma unroll
    for (int i = 0; i < 8; i++) {
        const int m = bm + ty * 8 + i;
        float4 r0, r1;
        r0.x = acc[i][0] + bvals[0]; r0.y = acc[i][1] + bvals[1];
        r0.z = acc[i][2] + bvals[2]; r0.w = acc[i][3] + bvals[3];
        r1.x = acc[i][4] + bvals[4]; r1.y = acc[i][5] + bvals[5];
        r1.z = acc[i][6] + bvals[6]; r1.w = acc[i][7] + bvals[7];
        *(float4*)(&out[(size_t)m * CM + n0])     = r0;
        *(float4*)(&out[(size_t)m * CM + n0 + 4]) = r1;
    }
}

// =============================================================================
extern "C" void kernel_launch(void* const* d_in, const int* in_sizes, int n_in,
                              void* d_out, int out_size) {
    (void)in_sizes; (void)n_in; (void)out_size;
    const float* x      = (const float*)d_in[0];
    const float* W_attn = (const float*)d_in[1];
    const float* b_attn = (const float*)d_in[2];
    const float* W_o    = (const float*)d_in[3];
    const float* b_o    = (const float*)d_in[4];
    float* out = (float*)d_out;

    // Idempotent, host-side, not stream-ordered -> graph-capture safe.
    cudaFuncSetAttribute(flash_kernel, cudaFuncAttributeMaxDynamicSharedMemorySize,
                         FLASH_SMEM);

    qkv_gemm<<<dim3(3 * CM / 128, MROWS / 128), 256>>>(x, W_attn, b_attn);
    flash_kernel<<<dim3(TT / 64, BB * NH), 256, FLASH_SMEM>>>();
    out_gemm<<<dim3(CM / 128, MROWS / 128), 256>>>(W_o, b_o, out);
}

// round 14
// speedup vs baseline: 2.8395x; 2.8395x over previous
#include <cuda_runtime.h>
#include <cuda_bf16.h>
#include <cstdint>
#include <math.h>

#define CM    1024          // d_model
#define NH    16            // heads
#define DK    64            // head dim
#define TT    2048          // seq len
#define BB    4             // batch
#define MROWS (BB * TT)     // 8192

// ---------------- scratch (device globals; no allocation APIs allowed) ----------
// Q/K/V as bf16 hi/lo pairs, layout [b*NH+h][t][64]
__device__ __align__(128) __nv_bfloat16 g_qh[BB * NH * TT * DK];
__device__ __align__(128) __nv_bfloat16 g_ql[BB * NH * TT * DK];
__device__ __align__(128) __nv_bfloat16 g_kh[BB * NH * TT * DK];
__device__ __align__(128) __nv_bfloat16 g_kl[BB * NH * TT * DK];
__device__ __align__(128) __nv_bfloat16 g_vh[BB * NH * TT * DK];
__device__ __align__(128) __nv_bfloat16 g_vl[BB * NH * TT * DK];
// inputs split hi/lo
__device__ __align__(128) __nv_bfloat16 g_xh[MROWS * CM];
__device__ __align__(128) __nv_bfloat16 g_xl[MROWS * CM];
__device__ __align__(128) __nv_bfloat16 g_wah[3 * CM * CM];
__device__ __align__(128) __nv_bfloat16 g_wal[3 * CM * CM];
__device__ __align__(128) __nv_bfloat16 g_woh[CM * CM];
__device__ __align__(128) __nv_bfloat16 g_wol[CM * CM];
// attention output split hi/lo, layout [b*T + t][h*64+d]
__device__ __align__(128) __nv_bfloat16 g_yh[MROWS * CM];
__device__ __align__(128) __nv_bfloat16 g_yl[MROWS * CM];

// ============================= PTX helpers ===================================
__device__ __forceinline__ uint32_t smem_u32(const void* p) {
    uint32_t a;
    asm("{ .reg .u64 t; cvta.to.shared.u64 t, %1; cvt.u32.u64 %0, t; }" : "=r"(a) : "l"(p));
    return a;
}
__device__ __forceinline__ void cpa16(uint32_t dst, const void* src) {
    asm volatile("cp.async.cg.shared.global [%0], [%1], 16;" :: "r"(dst), "l"(src));
}
__device__ __forceinline__ void cpa_commit() { asm volatile("cp.async.commit_group;"); }
template <int N>
__device__ __forceinline__ void cpa_wait() { asm volatile("cp.async.wait_group %0;" :: "n"(N)); }

__device__ __forceinline__ void ldsm_x4(uint32_t& r0, uint32_t& r1, uint32_t& r2,
                                        uint32_t& r3, uint32_t addr) {
    asm volatile("ldmatrix.sync.aligned.m8n8.x4.shared.b16 {%0,%1,%2,%3}, [%4];"
                 : "=r"(r0), "=r"(r1), "=r"(r2), "=r"(r3) : "r"(addr));
}
__device__ __forceinline__ void ldsm_x2(uint32_t& r0, uint32_t& r1, uint32_t addr) {
    asm volatile("ldmatrix.sync.aligned.m8n8.x2.shared.b16 {%0,%1}, [%2];"
                 : "=r"(r0), "=r"(r1) : "r"(addr));
}
__device__ __forceinline__ void ldsm_x2_trans(uint32_t& r0, uint32_t& r1, uint32_t addr) {
    asm volatile("ldmatrix.sync.aligned.m8n8.x2.trans.shared.b16 {%0,%1}, [%2];"
                 : "=r"(r0), "=r"(r1) : "r"(addr));
}
__device__ __forceinline__ void mma16816(float& d0, float& d1, float& d2, float& d3,
                                         uint32_t a0, uint32_t a1, uint32_t a2, uint32_t a3,
                                         uint32_t b0, uint32_t b1) {
    asm volatile(
        "mma.sync.aligned.m16n8k16.row.col.f32.bf16.bf16.f32 "
        "{%0,%1,%2,%3}, {%4,%5,%6,%7}, {%8,%9}, {%0,%1,%2,%3};"
        : "+f"(d0), "+f"(d1), "+f"(d2), "+f"(d3)
        : "r"(a0), "r"(a1), "r"(a2), "r"(a3), "r"(b0), "r"(b1));
}

// swizzle for 128B rows (64 bf16) split into 8 chunks of 16B
__device__ __forceinline__ uint32_t swz(int row, int chunk) {
    return (uint32_t)(row * 128 + ((chunk ^ (row & 7)) << 4));
}

// split pair (x,y) -> packed bf16x2 hi and lo
__device__ __forceinline__ void pack2(float x, float y, uint32_t& hi, uint32_t& lo) {
    __nv_bfloat16 hx = __float2bfloat16(x), hy = __float2bfloat16(y);
    __nv_bfloat16 lx = __float2bfloat16(x - __bfloat162float(hx));
    __nv_bfloat16 ly = __float2bfloat16(y - __bfloat162float(hy));
    __nv_bfloat162 ph; ph.x = hx; ph.y = hy;
    __nv_bfloat162 pl; pl.x = lx; pl.y = ly;
    hi = *(uint32_t*)&ph;
    lo = *(uint32_t*)&pl;
}

// =============================================================================
// split: fp32 -> bf16 hi + bf16 lo (separate arrays), vectorized x4
// =============================================================================
__global__ void split_kernel(const float* __restrict__ in,
                             __nv_bfloat16* __restrict__ hi,
                             __nv_bfloat16* __restrict__ lo, int n4) {
    int i = blockIdx.x * blockDim.x + threadIdx.x;
    if (i >= n4) return;
    float4 v = ((const float4*)in)[i];
    uint32_t h0, l0, h1, l1;
    pack2(v.x, v.y, h0, l0);
    pack2(v.z, v.w, h1, l1);
    ((uint32_t*)hi)[i * 2]     = h0;
    ((uint32_t*)hi)[i * 2 + 1] = h1;
    ((uint32_t*)lo)[i * 2]     = l0;
    ((uint32_t*)lo)[i * 2 + 1] = l1;
}

// =============================================================================
// HMMA GEMM: C[m,n] = sum_k A[m,k]*B[n,k] + bias[n], with split-precision
// 3-segment schedule over virtual K=3*CM: Ah*Bh + Al*Bh + Ah*Bl.
// BM=BN=128, BK=64, 3-stage cp.async, 8 warps (2x4), warp tile 64x32.
// mode 0: split-write into g_{q,k,v}{h,l} [b,h,t,d]; mode 1: fp32 outp.
// =============================================================================
#define NSTAGE 3
#define STAGE_BYTES 32768                     // A 16KB + B 16KB
#define MM_SMEM (NSTAGE * STAGE_BYTES)        // 96KB
#define NIT 48                                // 3 segments x 16 chunks

__global__ __launch_bounds__(256, 2) void mm_tc(
    const __nv_bfloat16* __restrict__ Ahi, const __nv_bfloat16* __restrict__ Alo,
    const __nv_bfloat16* __restrict__ Bhi, const __nv_bfloat16* __restrict__ Blo,
    const float* __restrict__ bias, float* __restrict__ outp, int mode)
{
    extern __shared__ char dynsm[];
    const uint32_t sb = smem_u32(dynsm);

    const int tid = threadIdx.x;
    const int wid = tid >> 5, lane = tid & 31;
    const int wm = wid & 1, wn = wid >> 1;     // warp tile: (wm*64, wn*32)
    const int bm = blockIdx.y * 128;
    const int bn = blockIdx.x * 128;

    const int lrow = tid >> 1;                 // 0..127
    const int lcb  = (tid & 1) * 4;            // chunk base 0 or 4

    auto load_tile = [&](int kiter, int s) {
        const int seg = kiter >> 4;
        const int ko  = (kiter & 15) * 64;
        const __nv_bfloat16* Ab = (seg == 1) ? Alo : Ahi;
        const __nv_bfloat16* Bb = (seg == 2) ? Blo : Bhi;
        const __nv_bfloat16* ga = Ab + (size_t)(bm + lrow) * CM + ko + lcb * 8;
        const __nv_bfloat16* gb = Bb + (size_t)(bn + lrow) * CM + ko + lcb * 8;
        const uint32_t stA = sb + s * STAGE_BYTES;
        const uint32_t stB = stA + 16384;
#pragma unroll
        for (int u = 0; u < 4; u++) {
            uint32_t sw = swz(lrow, lcb + u);
            cpa16(stA + sw, ga + u * 8);
            cpa16(stB + sw, gb + u * 8);
        }
        cpa_commit();
    };

    float acc[4][4][4];
#pragma unroll
    for (int mi = 0; mi < 4; mi++)
#pragma unroll
        for (int ni = 0; ni < 4; ni++)
#pragma unroll
            for (int e = 0; e < 4; e++) acc[mi][ni][e] = 0.f;

    load_tile(0, 0);
    load_tile(1, 1);

    const int arow = wm * 64 + (lane & 15);
    const int acol = lane >> 4;
    const int brow = wn * 32 + (lane & 7);
    const int bcol = (lane >> 3) & 1;

    for (int kiter = 0; kiter < NIT; kiter++) {
        if (kiter == NIT - 1) cpa_wait<0>(); else cpa_wait<1>();
        __syncthreads();

        const int s = kiter % NSTAGE;
        const uint32_t stA = sb + s * STAGE_BYTES;
        const uint32_t stB = stA + 16384;

#pragma unroll
        for (int kk = 0; kk < 4; kk++) {
            uint32_t bf[4][2];
#pragma unroll
            for (int ni = 0; ni < 4; ni++)
                ldsm_x2(bf[ni][0], bf[ni][1], stB + swz(brow + ni * 8, 2 * kk + bcol));
#pragma unroll
            for (int mi = 0; mi < 4; mi++) {
                uint32_t a0, a1, a2, a3;
                ldsm_x4(a0, a1, a2, a3, stA + swz(arow + mi * 16, 2 * kk + acol));
#pragma unroll
                for (int ni = 0; ni < 4; ni++)
                    mma16816(acc[mi][ni][0], acc[mi][ni][1], acc[mi][ni][2], acc[mi][ni][3],
                             a0, a1, a2, a3, bf[ni][0], bf[ni][1]);
            }
        }

        if (kiter + 2 < NIT) load_tile(kiter + 2, (kiter + 2) % NSTAGE);
    }

    // ---- epilogue ----
    const int qr = lane >> 2;
    const int qc = (lane & 3) * 2;
#pragma unroll
    for (int ni = 0; ni < 4; ni++) {
        const int n = bn + wn * 32 + ni * 8 + qc;
        const float b0 = bias[n], b1 = bias[n + 1];
        if (mode == 0) {
            const int part = n >> 10, rem = n & 1023;
            const int h = rem >> 6, d0 = rem & 63;
            __nv_bfloat16* hb = (part == 0) ? g_qh : (part == 1) ? g_kh : g_vh;
            __nv_bfloat16* lb = (part == 0) ? g_ql : (part == 1) ? g_kl : g_vl;
#pragma unroll
            for (int mi = 0; mi < 4; mi++) {
#pragma unroll
                for (int half = 0; half < 2; half++) {
                    const int m = bm + wm * 64 + mi * 16 + qr + half * 8;
                    const int bb = m >> 11, t = m & 2047;
                    const size_t off = (((size_t)(bb * NH + h)) * TT + t) * DK + d0;
                    uint32_t ph, pl;
                    pack2(acc[mi][ni][half * 2 + 0] + b0,
                          acc[mi][ni][half * 2 + 1] + b1, ph, pl);
                    *(uint32_t*)(hb + off) = ph;
                    *(uint32_t*)(lb + off) = pl;
                }
            }
        } else {
#pragma unroll
            for (int mi = 0; mi < 4; mi++) {
#pragma unroll
                for (int half = 0; half < 2; half++) {
                    const int m = bm + wm * 64 + mi * 16 + qr + half * 8;
                    float2 v;
                    v.x = acc[mi][ni][half * 2 + 0] + b0;
                    v.y = acc[mi][ni][half * 2 + 1] + b1;
                    *(float2*)(outp + (size_t)m * CM + n) = v;
                }
            }
        }
    }
}

// =============================================================================
// HMMA causal flash attention, split precision.
// CTA: 256 threads (8 warps), Br=128 queries (16 rows/warp), Bc=64 keys, d=64.
// S = Qh*Kh + Ql*Kh + Qh*Kl ; O += Ph*Vh + Pl*Vh + Ph*Vl (fp32 accumulators).
// P stays in registers (C-fragment == A-fragment layout).
// smem: Qh,Ql 32KB + 2 KV stages x (Kh,Kl,Vh,Vl) 32KB = 96KB.
// =============================================================================
#define FL_SMEM (32768 + 2 * 32768)           // 96KB

__global__ __launch_bounds__(256, 1) void flash_mma() {
    extern __shared__ char dynsm[];
    const uint32_t sb  = smem_u32(dynsm);      // Qh at +0, Ql at +16384
    const uint32_t kvb = sb + 32768;           // stages

    const int tid = threadIdx.x;
    const int wid = tid >> 5, lane = tid & 31;
    const int bh = blockIdx.y;
    const int i0 = (int)gridDim.x - 1 - (int)blockIdx.x;   // big tiles first
    const int bb = bh >> 4;
    const int h  = bh & 15;

    // ---- load Q (hi+lo) ----
    {
        const int r = tid >> 1, cb = (tid & 1) * 4;
        const size_t go = ((size_t)bh * TT + i0 * 128 + r) * DK + cb * 8;
#pragma unroll
        for (int u = 0; u < 4; u++) {
            uint32_t sw = swz(r, cb + u);
            cpa16(sb + sw,         g_qh + go + u * 8);
            cpa16(sb + 16384 + sw, g_ql + go + u * 8);
        }
        cpa_commit();
    }

    auto load_kv = [&](int jb, int st) {
        const uint32_t stg = kvb + st * 32768;
        const int r = tid >> 2, cb = (tid & 3) * 2;
        const size_t go = ((size_t)bh * TT + jb * 64 + r) * DK + cb * 8;
#pragma unroll
        for (int u = 0; u < 2; u++) {
            uint32_t sw = swz(r, cb + u);
            cpa16(stg + 0     + sw, g_kh + go + u * 8);
            cpa16(stg + 8192  + sw, g_kl + go + u * 8);
            cpa16(stg + 16384 + sw, g_vh + go + u * 8);
            cpa16(stg + 24576 + sw, g_vl + go + u * 8);
        }
        cpa_commit();
    };

    load_kv(0, 0);
    cpa_wait<0>();
    __syncthreads();

    // ---- Q fragments (held in regs for whole kernel) ----
    uint32_t qfh[4][4], qfl[4][4];
    {
        const int arow = wid * 16 + (lane & 15);
        const int acol = lane >> 4;
#pragma unroll
        for (int kc = 0; kc < 4; kc++) {
            ldsm_x4(qfh[kc][0], qfh[kc][1], qfh[kc][2], qfh[kc][3],
                    sb + swz(arow, 2 * kc + acol));
            ldsm_x4(qfl[kc][0], qfl[kc][1], qfl[kc][2], qfl[kc][3],
                    sb + 16384 + swz(arow, 2 * kc + acol));
        }
    }

    float o[8][4];
#pragma unroll
    for (int ni = 0; ni < 8; ni++)
#pragma unroll
        for (int e = 0; e < 4; e++) o[ni][e] = 0.f;
    float m0 = -1e30f, m1 = -1e30f, l0 = 0.f, l1 = 0.f;

    const int nblk = 2 * i0 + 2;
    const int qabs0 = i0 * 128 + wid * 16 + (lane >> 2);   // row of c0/c1; +8 for c2/c3

    for (int jb = 0; jb < nblk; jb++) {
        const uint32_t stg = kvb + (jb & 1) * 32768;
        if (jb + 1 < nblk) load_kv(jb + 1, (jb + 1) & 1);

        // ---- S = Q K^T (3 split terms) ----
        float s[8][4];
#pragma unroll
        for (int ni = 0; ni < 8; ni++)
#pragma unroll
            for (int e = 0; e < 4; e++) s[ni][e] = 0.f;

        const int krow = lane & 7;
        const int kcolb = (lane >> 3) & 1;
#pragma unroll
        for (int kc = 0; kc < 4; kc++) {
#pragma unroll
            for (int ni = 0; ni < 8; ni++) {
                uint32_t b0, b1;
                uint32_t sw = swz(ni * 8 + krow, 2 * kc + kcolb);
                ldsm_x2(b0, b1, stg + sw);            // Kh
                mma16816(s[ni][0], s[ni][1], s[ni][2], s[ni][3],
                         qfh[kc][0], qfh[kc][1], qfh[kc][2], qfh[kc][3], b0, b1);
                mma16816(s[ni][0], s[ni][1], s[ni][2], s[ni][3],
                         qfl[kc][0], qfl[kc][1], qfl[kc][2], qfl[kc][3], b0, b1);
                ldsm_x2(b0, b1, stg + 8192 + sw);     // Kl
                mma16816(s[ni][0], s[ni][1], s[ni][2], s[ni][3],
                         qfh[kc][0], qfh[kc][1], qfh[kc][2], qfh[kc][3], b0, b1);
            }
        }

        // ---- scale + causal mask ----
        const bool masked = (jb >= 2 * i0);
#pragma unroll
        for (int ni = 0; ni < 8; ni++)
#pragma unroll
            for (int e = 0; e < 4; e++) {
                float sc = s[ni][e] * 0.125f;
                if (masked) {
                    int kab = jb * 64 + ni * 8 + (lane & 3) * 2 + (e & 1);
                    int qab = qabs0 + (e >> 1) * 8;
                    if (kab > qab) sc = -1e30f;
                }
                s[ni][e] = sc;
            }

        // ---- online softmax ----
        float mx0 = -1e30f, mx1 = -1e30f;
#pragma unroll
        for (int ni = 0; ni < 8; ni++) {
            mx0 = fmaxf(mx0, fmaxf(s[ni][0], s[ni][1]));
            mx1 = fmaxf(mx1, fmaxf(s[ni][2], s[ni][3]));
        }
        mx0 = fmaxf(mx0, __shfl_xor_sync(0xffffffffu, mx0, 1));
        mx0 = fmaxf(mx0, __shfl_xor_sync(0xffffffffu, mx0, 2));
        mx1 = fmaxf(mx1, __shfl_xor_sync(0xffffffffu, mx1, 1));
        mx1 = fmaxf(mx1, __shfl_xor_sync(0xffffffffu, mx1, 2));
        const float mn0 = fmaxf(m0, mx0);
        const float mn1 = fmaxf(m1, mx1);
        const float al0 = __expf(m0 - mn0);
        const float al1 = __expf(m1 - mn1);
        float rs0 = 0.f, rs1 = 0.f;
#pragma unroll
        for (int ni = 0; ni < 8; ni++) {
            float p0 = __expf(s[ni][0] - mn0);
            float p1 = __expf(s[ni][1] - mn0);
            float p2 = __expf(s[ni][2] - mn1);
            float p3 = __expf(s[ni][3] - mn1);
            s[ni][0] = p0; s[ni][1] = p1; s[ni][2] = p2; s[ni][3] = p3;
            rs0 += p0 + p1;
            rs1 += p2 + p3;
        }
        rs0 += __shfl_xor_sync(0xffffffffu, rs0, 1);
        rs0 += __shfl_xor_sync(0xffffffffu, rs0, 2);
        rs1 += __shfl_xor_sync(0xffffffffu, rs1, 1);
        rs1 += __shfl_xor_sync(0xffffffffu, rs1, 2);
        l0 = l0 * al0 + rs0;
        l1 = l1 * al1 + rs1;
        m0 = mn0; m1 = mn1;
#pragma unroll
        for (int ni = 0; ni < 8; ni++) {
            o[ni][0] *= al0; o[ni][1] *= al0;
            o[ni][2] *= al1; o[ni][3] *= al1;
        }

        // ---- P -> bf16 hi/lo A-fragments (register-resident) ----
        uint32_t pfh[4][4], pfl[4][4];
#pragma unroll
        for (int kc = 0; kc < 4; kc++) {
            pack2(s[2 * kc][0],     s[2 * kc][1],     pfh[kc][0], pfl[kc][0]);
            pack2(s[2 * kc][2],     s[2 * kc][3],     pfh[kc][1], pfl[kc][1]);
            pack2(s[2 * kc + 1][0], s[2 * kc + 1][1], pfh[kc][2], pfl[kc][2]);
            pack2(s[2 * kc + 1][2], s[2 * kc + 1][3], pfh[kc][3], pfl[kc][3]);
        }

        // ---- O += P V (3 split terms), V via ldmatrix.trans ----
        const int vrow = lane & 15;
#pragma unroll
        for (int kc = 0; kc < 4; kc++) {
#pragma unroll
            for (int ni = 0; ni < 8; ni++) {
                uint32_t b0, b1;
                uint32_t sw = swz(16 * kc + vrow, ni);
                ldsm_x2_trans(b0, b1, stg + 16384 + sw);   // Vh
                mma16816(o[ni][0], o[ni][1], o[ni][2], o[ni][3],
                         pfh[kc][0], pfh[kc][1], pfh[kc][2], pfh[kc][3], b0, b1);
                mma16816(o[ni][0], o[ni][1], o[ni][2], o[ni][3],
                         pfl[kc][0], pfl[kc][1], pfl[kc][2], pfl[kc][3], b0, b1);
                ldsm_x2_trans(b0, b1, stg + 24576 + sw);   // Vl
                mma16816(o[ni][0], o[ni][1], o[ni][2], o[ni][3],
                         pfh[kc][0], pfh[kc][1], pfh[kc][2], pfh[kc][3], b0, b1);
            }
        }

        if (jb + 1 < nblk) { cpa_wait<0>(); __syncthreads(); }
    }

    // ---- epilogue: O/l -> y split hi/lo ----
    const float inv0 = 1.0f / l0;
    const float inv1 = 1.0f / l1;
    const int t0 = i0 * 128 + wid * 16 + (lane >> 2);
    const int colb = h * DK + (lane & 3) * 2;
#pragma unroll
    for (int ni = 0; ni < 8; ni++) {
        uint32_t ph, pl;
        const size_t r0 = ((size_t)bb * TT + t0) * CM + colb + ni * 8;
        const size_t r1 = ((size_t)bb * TT + t0 + 8) * CM + colb + ni * 8;
        pack2(o[ni][0] * inv0, o[ni][1] * inv0, ph, pl);
        *(uint32_t*)(g_yh + r0) = ph;
        *(uint32_t*)(g_yl + r0) = pl;
        pack2(o[ni][2] * inv1, o[ni][3] * inv1, ph, pl);
        *(uint32_t*)(g_yh + r1) = ph;
        *(uint32_t*)(g_yl + r1) = pl;
    }
}

// =============================================================================
extern "C" void kernel_launch(void* const* d_in, const int* in_sizes, int n_in,
                              void* d_out, int out_size) {
    (void)in_sizes; (void)n_in; (void)out_size;
    const float* x      = (const float*)d_in[0];
    const float* W_attn = (const float*)d_in[1];
    const float* b_attn = (const float*)d_in[2];
    const float* W_o    = (const float*)d_in[3];
    const float* b_o    = (const float*)d_in[4];
    float* out = (float*)d_out;

    cudaFuncSetAttribute(mm_tc, cudaFuncAttributeMaxDynamicSharedMemorySize, MM_SMEM);
    cudaFuncSetAttribute(flash_mma, cudaFuncAttributeMaxDynamicSharedMemorySize, FL_SMEM);

    __nv_bfloat16 *xh, *xl, *wah, *wal, *woh, *wol, *yh, *yl;
    cudaGetSymbolAddress((void**)&xh, g_xh);   cudaGetSymbolAddress((void**)&xl, g_xl);
    cudaGetSymbolAddress((void**)&wah, g_wah); cudaGetSymbolAddress((void**)&wal, g_wal);
    cudaGetSymbolAddress((void**)&woh, g_woh); cudaGetSymbolAddress((void**)&wol, g_wol);
    cudaGetSymbolAddress((void**)&yh, g_yh);   cudaGetSymbolAddress((void**)&yl, g_yl);

    const int n4x  = MROWS * CM / 4;
    const int n4wa = 3 * CM * CM / 4;
    const int n4wo = CM * CM / 4;

    split_kernel<<<(n4x + 255) / 256, 256>>>(x, xh, xl, n4x);
    split_kernel<<<(n4wa + 255) / 256, 256>>>(W_attn, wah, wal, n4wa);
    split_kernel<<<(n4wo + 255) / 256, 256>>>(W_o, woh, wol, n4wo);

    // QKV projection -> Q/K/V bf16 hi/lo
    mm_tc<<<dim3(3 * CM / 128, MROWS / 128), 256, MM_SMEM>>>(
        xh, xl, wah, wal, b_attn, nullptr, 0);

    // causal attention -> y bf16 hi/lo
    flash_mma<<<dim3(TT / 128, BB * NH), 256, FL_SMEM>>>();

    // output projection -> fp32 out
    mm_tc<<<dim3(CM / 128, MROWS / 128), 256, MM_SMEM>>>(
        yh, yl, woh, wol, b_o, out, 1);
}